// round 1
// baseline (speedup 1.0000x reference)
#include <cuda_runtime.h>
#include <cuda_bf16.h>
#include <math.h>

#define Nn 64
#define Ff 256
#define U 4096            // Nn*Nn
#define ROWS 128          // k-chunk rows per gemv block
#define GEMV_TPB 128      // threads per gemv block (1 element of chunk per thread)
#define JBLK 8            // U / (GEMV_TPB*4)
#define KBLK (U / ROWS)   // 32

// scratch (allocation-free rule: __device__ globals)
__device__ float g_x [3 * U];   // masked distance vectors (gemv1 input)
__device__ float g_v1[3 * U];   // gemv1 accumulator
__device__ float g_y2[3 * U];   // gemv2 accumulator

// ---------------------------------------------------------------------------
// Kernel 1: pairwise masked distances + zero-init of accumulators.
// One warp per (branch, i, j) pair. Coalesced over F.
// ---------------------------------------------------------------------------
__global__ void dist_kernel(const float* __restrict__ adj0,
                            const float* __restrict__ adj1,
                            const float* __restrict__ adj2,
                            const float* __restrict__ nv)
{
    int gtid = blockIdx.x * blockDim.x + threadIdx.x;
    // zero accumulators (3*U = 12288 elements)
    if (gtid < 3 * U) { g_v1[gtid] = 0.0f; g_y2[gtid] = 0.0f; }

    int wid  = gtid >> 5;          // global warp id: 0 .. 3*4096-1
    int lane = gtid & 31;
    if (wid >= 3 * U / 1) { /* unreachable with exact grid */ }

    int branch = wid >> 12;        // /4096
    int pair   = wid & (U - 1);
    int i = pair >> 6;
    int j = pair & 63;

    const float* adj = (branch == 0) ? adj0 : (branch == 1) ? adj1 : adj2;

    const float* ri = nv + i * Ff;
    const float* rj = nv + j * Ff;
    float s = 0.0f;
    #pragma unroll
    for (int f = lane; f < Ff; f += 32) {
        float d = __ldg(ri + f) - __ldg(rj + f);
        s = fmaf(d, d, s);
    }
    #pragma unroll
    for (int off = 16; off > 0; off >>= 1)
        s += __shfl_down_sync(0xffffffffu, s, off);

    if (lane == 0) {
        float a = __ldg(adj + pair);
        g_x[branch * U + pair] = (a == 1.0f) ? sqrtf(s) : 0.0f;
    }
}

// ---------------------------------------------------------------------------
// Kernel 2/3: sparse-input split-K GEMV with deterministic nonzero compaction.
//   y[b*U + j] += sum_i f(x[b*U+i]) * W_b[i*U + j]     (f = identity or relu)
// grid: (JBLK, KBLK, 3), block: GEMV_TPB. Thread owns 4 consecutive columns.
// ---------------------------------------------------------------------------
__global__ void gemv_kernel(const float* __restrict__ x,
                            const float* __restrict__ w0,
                            const float* __restrict__ w1,
                            const float* __restrict__ w2,
                            float* __restrict__ y,
                            int relu_x)
{
    __shared__ float sv[ROWS];
    __shared__ int   sidx[ROWS];
    __shared__ int   warp_off[(GEMV_TPB / 32) + 1];

    const int tid  = threadIdx.x;
    const int lane = tid & 31;
    const int w    = tid >> 5;
    const int b    = blockIdx.z;
    const int i0   = blockIdx.y * ROWS;
    const int j0   = blockIdx.x * (GEMV_TPB * 4) + tid * 4;

    const float* W = (b == 0) ? w0 : (b == 1) ? w1 : w2;

    // deterministic compaction of nonzero x entries in [i0, i0+ROWS)
    float v = x[b * U + i0 + tid];
    if (relu_x) v = fmaxf(v, 0.0f);
    bool nz = (v != 0.0f);
    unsigned m = __ballot_sync(0xffffffffu, nz);
    if (lane == 0) warp_off[w] = __popc(m);
    __syncthreads();
    if (tid == 0) {
        int s = 0;
        #pragma unroll
        for (int ww = 0; ww < GEMV_TPB / 32; ww++) {
            int c = warp_off[ww];
            warp_off[ww] = s;
            s += c;
        }
        warp_off[GEMV_TPB / 32] = s;
    }
    __syncthreads();
    if (nz) {
        int p = warp_off[w] + __popc(m & ((1u << lane) - 1u));
        sv[p]   = v;
        sidx[p] = i0 + tid;
    }
    __syncthreads();
    const int cnt = warp_off[GEMV_TPB / 32];

    const float* Wb = W + (size_t)j0;
    float4 acc = make_float4(0.f, 0.f, 0.f, 0.f);

    int k = 0;
    for (; k + 4 <= cnt; k += 4) {
        float4 a0 = __ldg((const float4*)(Wb + (size_t)sidx[k + 0] * U));
        float4 a1 = __ldg((const float4*)(Wb + (size_t)sidx[k + 1] * U));
        float4 a2 = __ldg((const float4*)(Wb + (size_t)sidx[k + 2] * U));
        float4 a3 = __ldg((const float4*)(Wb + (size_t)sidx[k + 3] * U));
        float c0 = sv[k + 0], c1 = sv[k + 1], c2 = sv[k + 2], c3 = sv[k + 3];
        acc.x = fmaf(c0, a0.x, acc.x); acc.y = fmaf(c0, a0.y, acc.y);
        acc.z = fmaf(c0, a0.z, acc.z); acc.w = fmaf(c0, a0.w, acc.w);
        acc.x = fmaf(c1, a1.x, acc.x); acc.y = fmaf(c1, a1.y, acc.y);
        acc.z = fmaf(c1, a1.z, acc.z); acc.w = fmaf(c1, a1.w, acc.w);
        acc.x = fmaf(c2, a2.x, acc.x); acc.y = fmaf(c2, a2.y, acc.y);
        acc.z = fmaf(c2, a2.z, acc.z); acc.w = fmaf(c2, a2.w, acc.w);
        acc.x = fmaf(c3, a3.x, acc.x); acc.y = fmaf(c3, a3.y, acc.y);
        acc.z = fmaf(c3, a3.z, acc.z); acc.w = fmaf(c3, a3.w, acc.w);
    }
    for (; k < cnt; k++) {
        float4 a0 = __ldg((const float4*)(Wb + (size_t)sidx[k] * U));
        float c0 = sv[k];
        acc.x = fmaf(c0, a0.x, acc.x); acc.y = fmaf(c0, a0.y, acc.y);
        acc.z = fmaf(c0, a0.z, acc.z); acc.w = fmaf(c0, a0.w, acc.w);
    }

    float* yp = y + b * U + j0;
    atomicAdd(yp + 0, acc.x);
    atomicAdd(yp + 1, acc.y);
    atomicAdd(yp + 2, acc.z);
    atomicAdd(yp + 3, acc.w);
}

// ---------------------------------------------------------------------------
// Kernel 4: final relu copy to output
// ---------------------------------------------------------------------------
__global__ void relu_out_kernel(float* __restrict__ out)
{
    int g = blockIdx.x * blockDim.x + threadIdx.x;
    if (g < 3 * U) out[g] = fmaxf(g_y2[g], 0.0f);
}

extern "C" void kernel_launch(void* const* d_in, const int* in_sizes, int n_in,
                              void* d_out, int out_size)
{
    const float* adj0 = (const float*)d_in[0];
    const float* adj1 = (const float*)d_in[1];
    const float* adj2 = (const float*)d_in[2];
    const float* nv   = (const float*)d_in[3];
    const float* w0_1 = (const float*)d_in[4];
    const float* w0_2 = (const float*)d_in[5];
    const float* w1_1 = (const float*)d_in[6];
    const float* w1_2 = (const float*)d_in[7];
    const float* w2_1 = (const float*)d_in[8];
    const float* w2_2 = (const float*)d_in[9];
    float* out = (float*)d_out;

    float *gx, *gv1, *gy2;
    cudaGetSymbolAddress((void**)&gx,  g_x);
    cudaGetSymbolAddress((void**)&gv1, g_v1);
    cudaGetSymbolAddress((void**)&gy2, g_y2);

    // 3*4096 warps -> 12288*32 threads / 256 = 1536 blocks
    dist_kernel<<<1536, 256>>>(adj0, adj1, adj2, nv);

    dim3 grid(JBLK, KBLK, 3);
    gemv_kernel<<<grid, GEMV_TPB>>>(gx,  w0_1, w1_1, w2_1, gv1, 0);
    gemv_kernel<<<grid, GEMV_TPB>>>(gv1, w0_2, w1_2, w2_2, gy2, 1);

    relu_out_kernel<<<(3 * U + 255) / 256, 256>>>(out);
}

// round 3
// speedup vs baseline: 1.0007x; 1.0007x over previous
#include <cuda_runtime.h>
#include <cuda_bf16.h>
#include <math.h>

#define Nn 64
#define Ff 256
#define U 4096            // Nn*Nn
#define ROWS 128          // k-chunk rows per gemv block
#define GEMV_TPB 128      // threads per gemv block
#define JBLK 8            // U / (GEMV_TPB*4)
#define KBLK (U / ROWS)   // 32

// scratch (allocation-free rule: __device__ globals)
__device__ float    g_x  [3 * U];     // masked distance vectors (gemv1 input)
__device__ float    g_v1 [3 * U];     // gemv1 accumulator
__device__ unsigned g_cnt[3 * JBLK];  // gemv2 epilogue completion counters

// ---------------------------------------------------------------------------
// Kernel 1: unique pairwise distances (computed ONCE, shared by 3 branches)
// + zero-init of gemv1 accumulator, d_out, and epilogue counters.
// One warp per (i,j) pair: 4096 warps. Coalesced over F.
// ---------------------------------------------------------------------------
__global__ void dist_kernel(const float* __restrict__ adj0,
                            const float* __restrict__ adj1,
                            const float* __restrict__ adj2,
                            const float* __restrict__ nv,
                            float* __restrict__ out)
{
    int gtid = blockIdx.x * blockDim.x + threadIdx.x;
    // zero accumulators + output (3*U = 12288 elements); zero counters
    if (gtid < 3 * U) { g_v1[gtid] = 0.0f; out[gtid] = 0.0f; }
    if (gtid < 3 * JBLK) g_cnt[gtid] = 0u;

    int pair = gtid >> 5;          // warp id = pair id: 0 .. 4095
    int lane = gtid & 31;
    int i = pair >> 6;
    int j = pair & 63;

    const float* ri = nv + i * Ff;
    const float* rj = nv + j * Ff;
    float s = 0.0f;
    #pragma unroll
    for (int f = lane; f < Ff; f += 32) {
        float d = __ldg(ri + f) - __ldg(rj + f);
        s = fmaf(d, d, s);
    }
    #pragma unroll
    for (int off = 16; off > 0; off >>= 1)
        s += __shfl_down_sync(0xffffffffu, s, off);

    if (lane == 0) {
        float d = sqrtf(s);
        g_x[0 * U + pair] = (__ldg(adj0 + pair) == 1.0f) ? d : 0.0f;
        g_x[1 * U + pair] = (__ldg(adj1 + pair) == 1.0f) ? d : 0.0f;
        g_x[2 * U + pair] = (__ldg(adj2 + pair) == 1.0f) ? d : 0.0f;
    }
}

// ---------------------------------------------------------------------------
// Kernel 2/3: sparse-input split-K GEMV with deterministic nonzero compaction.
//   y[b*U + j] += sum_i f(x[b*U+i]) * W_b[i*U + j]   (f = identity or relu)
// grid: (JBLK, KBLK, 3), block: GEMV_TPB. Thread owns 4 consecutive columns.
// FINAL_RELU: last split-K block per (b, jblk) applies ReLU in place on y.
// ---------------------------------------------------------------------------
template <int RELU_X, int FINAL_RELU>
__global__ void gemv_kernel(const float* __restrict__ x,
                            const float* __restrict__ w0,
                            const float* __restrict__ w1,
                            const float* __restrict__ w2,
                            float* __restrict__ y)
{
    __shared__ float sv[ROWS];
    __shared__ int   sidx[ROWS];
    __shared__ int   warp_off[(GEMV_TPB / 32) + 1];
    __shared__ int   s_last;

    const int tid  = threadIdx.x;
    const int lane = tid & 31;
    const int w    = tid >> 5;
    const int b    = blockIdx.z;
    const int i0   = blockIdx.y * ROWS;
    const int j0   = blockIdx.x * (GEMV_TPB * 4) + tid * 4;

    const float* W = (b == 0) ? w0 : (b == 1) ? w1 : w2;

    // deterministic compaction of nonzero x entries in [i0, i0+ROWS)
    float v = x[b * U + i0 + tid];
    if (RELU_X) v = fmaxf(v, 0.0f);
    bool nz = (v != 0.0f);
    unsigned m = __ballot_sync(0xffffffffu, nz);
    if (lane == 0) warp_off[w] = __popc(m);
    __syncthreads();
    if (tid == 0) {
        int s = 0;
        #pragma unroll
        for (int ww = 0; ww < GEMV_TPB / 32; ww++) {
            int c = warp_off[ww];
            warp_off[ww] = s;
            s += c;
        }
        warp_off[GEMV_TPB / 32] = s;
    }
    __syncthreads();
    if (nz) {
        int p = warp_off[w] + __popc(m & ((1u << lane) - 1u));
        sv[p]   = v;
        sidx[p] = i0 + tid;
    }
    __syncthreads();
    const int cnt = warp_off[GEMV_TPB / 32];

    const float* Wb = W + (size_t)j0;
    float4 acc = make_float4(0.f, 0.f, 0.f, 0.f);

    int k = 0;
    for (; k + 4 <= cnt; k += 4) {
        float4 a0 = __ldg((const float4*)(Wb + (size_t)sidx[k + 0] * U));
        float4 a1 = __ldg((const float4*)(Wb + (size_t)sidx[k + 1] * U));
        float4 a2 = __ldg((const float4*)(Wb + (size_t)sidx[k + 2] * U));
        float4 a3 = __ldg((const float4*)(Wb + (size_t)sidx[k + 3] * U));
        float c0 = sv[k + 0], c1 = sv[k + 1], c2 = sv[k + 2], c3 = sv[k + 3];
        acc.x = fmaf(c0, a0.x, acc.x); acc.y = fmaf(c0, a0.y, acc.y);
        acc.z = fmaf(c0, a0.z, acc.z); acc.w = fmaf(c0, a0.w, acc.w);
        acc.x = fmaf(c1, a1.x, acc.x); acc.y = fmaf(c1, a1.y, acc.y);
        acc.z = fmaf(c1, a1.z, acc.z); acc.w = fmaf(c1, a1.w, acc.w);
        acc.x = fmaf(c2, a2.x, acc.x); acc.y = fmaf(c2, a2.y, acc.y);
        acc.z = fmaf(c2, a2.z, acc.z); acc.w = fmaf(c2, a2.w, acc.w);
        acc.x = fmaf(c3, a3.x, acc.x); acc.y = fmaf(c3, a3.y, acc.y);
        acc.z = fmaf(c3, a3.z, acc.z); acc.w = fmaf(c3, a3.w, acc.w);
    }
    for (; k < cnt; k++) {
        float4 a0 = __ldg((const float4*)(Wb + (size_t)sidx[k] * U));
        float c0 = sv[k];
        acc.x = fmaf(c0, a0.x, acc.x); acc.y = fmaf(c0, a0.y, acc.y);
        acc.z = fmaf(c0, a0.z, acc.z); acc.w = fmaf(c0, a0.w, acc.w);
    }

    float* yp = y + b * U + j0;
    atomicAdd(yp + 0, acc.x);
    atomicAdd(yp + 1, acc.y);
    atomicAdd(yp + 2, acc.z);
    atomicAdd(yp + 3, acc.w);

    if (FINAL_RELU) {
        // last split-K block for this (b, jblk) applies ReLU in place
        __threadfence();
        __syncthreads();
        if (tid == 0) {
            unsigned old = atomicAdd(&g_cnt[b * JBLK + blockIdx.x], 1u);
            s_last = (old == KBLK - 1) ? 1 : 0;
        }
        __syncthreads();
        if (s_last) {
            // re-read through L2 (atomics completed there)
            float r0 = __ldcg(yp + 0);
            float r1 = __ldcg(yp + 1);
            float r2 = __ldcg(yp + 2);
            float r3 = __ldcg(yp + 3);
            yp[0] = fmaxf(r0, 0.0f);
            yp[1] = fmaxf(r1, 0.0f);
            yp[2] = fmaxf(r2, 0.0f);
            yp[3] = fmaxf(r3, 0.0f);
        }
    }
}

extern "C" void kernel_launch(void* const* d_in, const int* in_sizes, int n_in,
                              void* d_out, int out_size)
{
    const float* adj0 = (const float*)d_in[0];
    const float* adj1 = (const float*)d_in[1];
    const float* adj2 = (const float*)d_in[2];
    const float* nv   = (const float*)d_in[3];
    const float* w0_1 = (const float*)d_in[4];
    const float* w0_2 = (const float*)d_in[5];
    const float* w1_1 = (const float*)d_in[6];
    const float* w1_2 = (const float*)d_in[7];
    const float* w2_1 = (const float*)d_in[8];
    const float* w2_2 = (const float*)d_in[9];
    float* out = (float*)d_out;

    float *gx, *gv1;
    cudaGetSymbolAddress((void**)&gx,  g_x);
    cudaGetSymbolAddress((void**)&gv1, g_v1);

    // 4096 pair-warps -> 4096*32/256 = 512 blocks
    dist_kernel<<<512, 256>>>(adj0, adj1, adj2, nv, out);

    dim3 grid(JBLK, KBLK, 3);
    gemv_kernel<0, 0><<<grid, GEMV_TPB>>>(gx,  w0_1, w1_1, w2_1, gv1);
    gemv_kernel<1, 1><<<grid, GEMV_TPB>>>(gv1, w0_2, w1_2, w2_2, out);
}

// round 5
// speedup vs baseline: 1.0300x; 1.0293x over previous
#include <cuda_runtime.h>
#include <cuda_bf16.h>
#include <math.h>

#define Nn 64
#define Ff 256
#define U 4096            // Nn*Nn
#define ROWS 128          // k-chunk rows per gemv block
#define GEMV_TPB 128      // threads per gemv block
#define JBLK 8            // U / (GEMV_TPB*4)
#define KBLK (U / ROWS)   // 32

// scratch (allocation-free rule: __device__ globals)
__device__ float    g_x  [3 * U];     // masked distance vectors (gemv1 input)
__device__ float    g_v1 [3 * U];     // gemv1 accumulator
__device__ unsigned g_cnt[3 * JBLK];  // gemv2 epilogue completion counters

// ---------------------------------------------------------------------------
// Kernel 1: unique pairwise distances (computed once, shared by 3 branches)
// + zero-init of gemv1 accumulator, d_out, and epilogue counters.
// One warp per (i,j) pair; float4-vectorized over F (4 independent LDG.128/lane).
// ---------------------------------------------------------------------------
__global__ void dist_kernel(const float* __restrict__ adj0,
                            const float* __restrict__ adj1,
                            const float* __restrict__ adj2,
                            const float* __restrict__ nv,
                            float* __restrict__ out)
{
    int gtid = blockIdx.x * blockDim.x + threadIdx.x;
    if (gtid < 3 * U) { g_v1[gtid] = 0.0f; out[gtid] = 0.0f; }
    if (gtid < 3 * JBLK) g_cnt[gtid] = 0u;

    int pair = gtid >> 5;          // warp id = pair id: 0 .. 4095
    int lane = gtid & 31;
    int i = pair >> 6;
    int j = pair & 63;

    const float4* ri = (const float4*)(nv + i * Ff);   // 64 float4s per row
    const float4* rj = (const float4*)(nv + j * Ff);

    float4 a0 = __ldg(ri + lane);
    float4 a1 = __ldg(ri + lane + 32);
    float4 b0 = __ldg(rj + lane);
    float4 b1 = __ldg(rj + lane + 32);

    float s = 0.0f;
    float d;
    d = a0.x - b0.x; s = fmaf(d, d, s);
    d = a0.y - b0.y; s = fmaf(d, d, s);
    d = a0.z - b0.z; s = fmaf(d, d, s);
    d = a0.w - b0.w; s = fmaf(d, d, s);
    d = a1.x - b1.x; s = fmaf(d, d, s);
    d = a1.y - b1.y; s = fmaf(d, d, s);
    d = a1.z - b1.z; s = fmaf(d, d, s);
    d = a1.w - b1.w; s = fmaf(d, d, s);

    #pragma unroll
    for (int off = 16; off > 0; off >>= 1)
        s += __shfl_down_sync(0xffffffffu, s, off);

    if (lane == 0) {
        float dist = sqrtf(s);
        g_x[0 * U + pair] = (__ldg(adj0 + pair) == 1.0f) ? dist : 0.0f;
        g_x[1 * U + pair] = (__ldg(adj1 + pair) == 1.0f) ? dist : 0.0f;
        g_x[2 * U + pair] = (__ldg(adj2 + pair) == 1.0f) ? dist : 0.0f;
    }
}

// ---------------------------------------------------------------------------
// Kernel 2/3: sparse-input split-K GEMV, nonzero row compaction, 8-deep unroll
// (8 outstanding LDG.128 per thread -> Little's-law BW cap ~10 TB/s > DRAM).
//   y[b*U + j] += sum_i f(x[b*U+i]) * W_b[i*U + j]   (f = identity or relu)
// grid: (JBLK, KBLK, 3), block: GEMV_TPB. Thread owns 4 consecutive columns.
// ---------------------------------------------------------------------------
template <int RELU_X, int FINAL_RELU>
__global__ void gemv_kernel(const float* __restrict__ x,
                            const float* __restrict__ w0,
                            const float* __restrict__ w1,
                            const float* __restrict__ w2,
                            float* __restrict__ y)
{
    __shared__ float sv[ROWS];
    __shared__ int   sidx[ROWS];
    __shared__ int   warp_off[(GEMV_TPB / 32) + 1];
    __shared__ int   s_last;

    const int tid  = threadIdx.x;
    const int lane = tid & 31;
    const int w    = tid >> 5;
    const int b    = blockIdx.z;
    const int i0   = blockIdx.y * ROWS;
    const int j0   = blockIdx.x * (GEMV_TPB * 4) + tid * 4;

    const float* W = (b == 0) ? w0 : (b == 1) ? w1 : w2;

    // deterministic compaction of nonzero x entries in [i0, i0+ROWS)
    float v = x[b * U + i0 + tid];
    if (RELU_X) v = fmaxf(v, 0.0f);
    bool nz = (v != 0.0f);
    unsigned m = __ballot_sync(0xffffffffu, nz);
    if (lane == 0) warp_off[w] = __popc(m);
    __syncthreads();
    if (tid == 0) {
        int s = 0;
        #pragma unroll
        for (int ww = 0; ww < GEMV_TPB / 32; ww++) {
            int c = warp_off[ww];
            warp_off[ww] = s;
            s += c;
        }
        warp_off[GEMV_TPB / 32] = s;
    }
    __syncthreads();
    if (nz) {
        int p = warp_off[w] + __popc(m & ((1u << lane) - 1u));
        sv[p]   = v;
        sidx[p] = i0 + tid;
    }
    __syncthreads();
    const int cnt = warp_off[GEMV_TPB / 32];

    const float* Wb = W + (size_t)j0;
    float4 acc = make_float4(0.f, 0.f, 0.f, 0.f);

    int k = 0;
    for (; k + 8 <= cnt; k += 8) {
        // gather indices first (LDS), then issue all 8 LDG.128 back-to-back
        int r0 = sidx[k + 0], r1 = sidx[k + 1], r2 = sidx[k + 2], r3 = sidx[k + 3];
        int r4 = sidx[k + 4], r5 = sidx[k + 5], r6 = sidx[k + 6], r7 = sidx[k + 7];
        float4 a0 = __ldg((const float4*)(Wb + (size_t)r0 * U));
        float4 a1 = __ldg((const float4*)(Wb + (size_t)r1 * U));
        float4 a2 = __ldg((const float4*)(Wb + (size_t)r2 * U));
        float4 a3 = __ldg((const float4*)(Wb + (size_t)r3 * U));
        float4 a4 = __ldg((const float4*)(Wb + (size_t)r4 * U));
        float4 a5 = __ldg((const float4*)(Wb + (size_t)r5 * U));
        float4 a6 = __ldg((const float4*)(Wb + (size_t)r6 * U));
        float4 a7 = __ldg((const float4*)(Wb + (size_t)r7 * U));
        float c0 = sv[k + 0], c1 = sv[k + 1], c2 = sv[k + 2], c3 = sv[k + 3];
        float c4 = sv[k + 4], c5 = sv[k + 5], c6 = sv[k + 6], c7 = sv[k + 7];
        acc.x = fmaf(c0, a0.x, acc.x); acc.y = fmaf(c0, a0.y, acc.y);
        acc.z = fmaf(c0, a0.z, acc.z); acc.w = fmaf(c0, a0.w, acc.w);
        acc.x = fmaf(c1, a1.x, acc.x); acc.y = fmaf(c1, a1.y, acc.y);
        acc.z = fmaf(c1, a1.z, acc.z); acc.w = fmaf(c1, a1.w, acc.w);
        acc.x = fmaf(c2, a2.x, acc.x); acc.y = fmaf(c2, a2.y, acc.y);
        acc.z = fmaf(c2, a2.z, acc.z); acc.w = fmaf(c2, a2.w, acc.w);
        acc.x = fmaf(c3, a3.x, acc.x); acc.y = fmaf(c3, a3.y, acc.y);
        acc.z = fmaf(c3, a3.z, acc.z); acc.w = fmaf(c3, a3.w, acc.w);
        acc.x = fmaf(c4, a4.x, acc.x); acc.y = fmaf(c4, a4.y, acc.y);
        acc.z = fmaf(c4, a4.z, acc.z); acc.w = fmaf(c4, a4.w, acc.w);
        acc.x = fmaf(c5, a5.x, acc.x); acc.y = fmaf(c5, a5.y, acc.y);
        acc.z = fmaf(c5, a5.z, acc.z); acc.w = fmaf(c5, a5.w, acc.w);
        acc.x = fmaf(c6, a6.x, acc.x); acc.y = fmaf(c6, a6.y, acc.y);
        acc.z = fmaf(c6, a6.z, acc.z); acc.w = fmaf(c6, a6.w, acc.w);
        acc.x = fmaf(c7, a7.x, acc.x); acc.y = fmaf(c7, a7.y, acc.y);
        acc.z = fmaf(c7, a7.z, acc.z); acc.w = fmaf(c7, a7.w, acc.w);
    }
    for (; k < cnt; k++) {
        float4 a0 = __ldg((const float4*)(Wb + (size_t)sidx[k] * U));
        float c0 = sv[k];
        acc.x = fmaf(c0, a0.x, acc.x); acc.y = fmaf(c0, a0.y, acc.y);
        acc.z = fmaf(c0, a0.z, acc.z); acc.w = fmaf(c0, a0.w, acc.w);
    }

    float* yp = y + b * U + j0;
    atomicAdd(yp + 0, acc.x);
    atomicAdd(yp + 1, acc.y);
    atomicAdd(yp + 2, acc.z);
    atomicAdd(yp + 3, acc.w);

    if (FINAL_RELU) {
        __threadfence();
        __syncthreads();
        if (tid == 0) {
            unsigned old = atomicAdd(&g_cnt[b * JBLK + blockIdx.x], 1u);
            s_last = (old == KBLK - 1) ? 1 : 0;
        }
        __syncthreads();
        if (s_last) {
            float r0 = __ldcg(yp + 0);
            float r1 = __ldcg(yp + 1);
            float r2 = __ldcg(yp + 2);
            float r3 = __ldcg(yp + 3);
            yp[0] = fmaxf(r0, 0.0f);
            yp[1] = fmaxf(r1, 0.0f);
            yp[2] = fmaxf(r2, 0.0f);
            yp[3] = fmaxf(r3, 0.0f);
        }
    }
}

extern "C" void kernel_launch(void* const* d_in, const int* in_sizes, int n_in,
                              void* d_out, int out_size)
{
    const float* adj0 = (const float*)d_in[0];
    const float* adj1 = (const float*)d_in[1];
    const float* adj2 = (const float*)d_in[2];
    const float* nv   = (const float*)d_in[3];
    const float* w0_1 = (const float*)d_in[4];
    const float* w0_2 = (const float*)d_in[5];
    const float* w1_1 = (const float*)d_in[6];
    const float* w1_2 = (const float*)d_in[7];
    const float* w2_1 = (const float*)d_in[8];
    const float* w2_2 = (const float*)d_in[9];
    float* out = (float*)d_out;

    float *gx, *gv1;
    cudaGetSymbolAddress((void**)&gx,  g_x);
    cudaGetSymbolAddress((void**)&gv1, g_v1);

    dist_kernel<<<512, 256>>>(adj0, adj1, adj2, nv, out);

    dim3 grid(JBLK, KBLK, 3);
    gemv_kernel<0, 0><<<grid, GEMV_TPB>>>(gx,  w0_1, w1_1, w2_1, gv1);
    gemv_kernel<1, 1><<<grid, GEMV_TPB>>>(gv1, w0_2, w1_2, w2_2, out);
}

// round 9
// speedup vs baseline: 1.0395x; 1.0092x over previous
#include <cuda_runtime.h>
#include <cuda_bf16.h>
#include <cstdint>
#include <math.h>

#define Nn 64
#define Ff 256
#define U 4096            // Nn*Nn
#define ROWS 128          // k-chunk rows per gemv block
#define GEMV_TPB 128      // threads per gemv block
#define JBLK 8            // U / (GEMV_TPB*4)
#define KBLK (U / ROWS)   // 32
#define DEPTH 16          // cp.async pipeline stages (rows in flight per block)

// scratch (allocation-free rule: __device__ globals)
__device__ float    g_x  [3 * U];     // masked distance vectors (gemv1 input)
__device__ float    g_v1 [3 * U];     // gemv1 accumulator
__device__ unsigned g_cnt[3 * JBLK];  // gemv2 epilogue completion counters

// ---------------- cp.async helpers ----------------
__device__ __forceinline__ void cp_async16(void* s, const void* g)
{
    unsigned int sa = (unsigned int)__cvta_generic_to_shared(s);
    asm volatile("cp.async.cg.shared.global [%0], [%1], 16;" :: "r"(sa), "l"(g));
}
__device__ __forceinline__ void cp_commit()
{
    asm volatile("cp.async.commit_group;" ::: "memory");
}
template <int N> __device__ __forceinline__ void cp_wait()
{
    asm volatile("cp.async.wait_group %0;" :: "n"(N) : "memory");
}

// ---------------------------------------------------------------------------
// Kernel 1: unique pairwise distances (computed once, shared by 3 branches)
// + zero-init of gemv1 accumulator, d_out, and epilogue counters.
// ---------------------------------------------------------------------------
__global__ void dist_kernel(const float* __restrict__ adj0,
                            const float* __restrict__ adj1,
                            const float* __restrict__ adj2,
                            const float* __restrict__ nv,
                            float* __restrict__ out)
{
    int gtid = blockIdx.x * blockDim.x + threadIdx.x;
    if (gtid < 3 * U) { g_v1[gtid] = 0.0f; out[gtid] = 0.0f; }
    if (gtid < 3 * JBLK) g_cnt[gtid] = 0u;

    int pair = gtid >> 5;          // warp id = pair id: 0 .. 4095
    int lane = gtid & 31;
    int i = pair >> 6;
    int j = pair & 63;

    const float4* ri = (const float4*)(nv + i * Ff);   // 64 float4s per row
    const float4* rj = (const float4*)(nv + j * Ff);

    float4 a0 = __ldg(ri + lane);
    float4 a1 = __ldg(ri + lane + 32);
    float4 b0 = __ldg(rj + lane);
    float4 b1 = __ldg(rj + lane + 32);

    float s = 0.0f;
    float d;
    d = a0.x - b0.x; s = fmaf(d, d, s);
    d = a0.y - b0.y; s = fmaf(d, d, s);
    d = a0.z - b0.z; s = fmaf(d, d, s);
    d = a0.w - b0.w; s = fmaf(d, d, s);
    d = a1.x - b1.x; s = fmaf(d, d, s);
    d = a1.y - b1.y; s = fmaf(d, d, s);
    d = a1.z - b1.z; s = fmaf(d, d, s);
    d = a1.w - b1.w; s = fmaf(d, d, s);

    #pragma unroll
    for (int off = 16; off > 0; off >>= 1)
        s += __shfl_down_sync(0xffffffffu, s, off);

    if (lane == 0) {
        float dist = sqrtf(s);
        g_x[0 * U + pair] = (__ldg(adj0 + pair) == 1.0f) ? dist : 0.0f;
        g_x[1 * U + pair] = (__ldg(adj1 + pair) == 1.0f) ? dist : 0.0f;
        g_x[2 * U + pair] = (__ldg(adj2 + pair) == 1.0f) ? dist : 0.0f;
    }
}

// ---------------------------------------------------------------------------
// Kernel 2/3: sparse-input split-K GEMV.
// Nonzero row compaction, then a DEPTH-stage cp.async smem pipeline:
// thread t stages W[row, j0..j0+3] (16B) for DEPTH rows ahead of the FMA
// consumer. Each thread consumes only its own cp.async data -> no barriers.
//   y[b*U + j] += sum_i f(x[b*U+i]) * W_b[i*U + j]   (f = identity or relu)
// grid: (JBLK, KBLK, 3), block: GEMV_TPB. Thread owns 4 consecutive columns.
// ---------------------------------------------------------------------------
template <int RELU_X, int FINAL_RELU>
__global__ void __launch_bounds__(GEMV_TPB)
gemv_kernel(const float* __restrict__ x,
            const float* __restrict__ w0,
            const float* __restrict__ w1,
            const float* __restrict__ w2,
            float* __restrict__ y)
{
    __shared__ float4 stage[DEPTH][GEMV_TPB];   // 16 * 128 * 16B = 32 KB
    __shared__ float  sv[ROWS];
    __shared__ int    sidx[ROWS];
    __shared__ int    warp_off[(GEMV_TPB / 32) + 1];
    __shared__ int    s_last;

    const int tid  = threadIdx.x;
    const int lane = tid & 31;
    const int w    = tid >> 5;
    const int b    = blockIdx.z;
    const int i0   = blockIdx.y * ROWS;
    const int j0   = blockIdx.x * (GEMV_TPB * 4) + tid * 4;

    const float* W = (b == 0) ? w0 : (b == 1) ? w1 : w2;

    // deterministic compaction of nonzero x entries in [i0, i0+ROWS)
    float v = x[b * U + i0 + tid];
    if (RELU_X) v = fmaxf(v, 0.0f);
    bool nz = (v != 0.0f);
    unsigned m = __ballot_sync(0xffffffffu, nz);
    if (lane == 0) warp_off[w] = __popc(m);
    __syncthreads();
    if (tid == 0) {
        int s = 0;
        #pragma unroll
        for (int ww = 0; ww < GEMV_TPB / 32; ww++) {
            int c = warp_off[ww];
            warp_off[ww] = s;
            s += c;
        }
        warp_off[GEMV_TPB / 32] = s;
    }
    __syncthreads();
    if (nz) {
        int p = warp_off[w] + __popc(m & ((1u << lane) - 1u));
        sv[p]   = v;
        sidx[p] = i0 + tid;
    }
    __syncthreads();
    const int cnt = warp_off[GEMV_TPB / 32];

    const float* Wb = W + (size_t)j0;
    float4 acc = make_float4(0.f, 0.f, 0.f, 0.f);

    // ---- prologue: fill the pipeline (always commit, even empty groups) ----
    #pragma unroll
    for (int s = 0; s < DEPTH; s++) {
        if (s < cnt)
            cp_async16(&stage[s][tid], Wb + (size_t)sidx[s] * U);
        cp_commit();
    }

    // ---- steady state: one wait + one consume + one issue per row ----
    // Invariant: before iter k, committed groups = DEPTH + k, so
    // wait_group(DEPTH-1) guarantees group k (row k) has landed.
    for (int k = 0; k < cnt; k++) {
        cp_wait<DEPTH - 1>();
        float4 a = stage[k & (DEPTH - 1)][tid];
        float  c = sv[k];
        int n = k + DEPTH;
        if (n < cnt)
            cp_async16(&stage[n & (DEPTH - 1)][tid], Wb + (size_t)sidx[n] * U);
        cp_commit();
        acc.x = fmaf(c, a.x, acc.x);
        acc.y = fmaf(c, a.y, acc.y);
        acc.z = fmaf(c, a.z, acc.z);
        acc.w = fmaf(c, a.w, acc.w);
    }
    cp_wait<0>();

    float* yp = y + b * U + j0;
    atomicAdd(yp + 0, acc.x);
    atomicAdd(yp + 1, acc.y);
    atomicAdd(yp + 2, acc.z);
    atomicAdd(yp + 3, acc.w);

    if (FINAL_RELU) {
        __threadfence();
        __syncthreads();
        if (tid == 0) {
            unsigned old = atomicAdd(&g_cnt[b * JBLK + blockIdx.x], 1u);
            s_last = (old == KBLK - 1) ? 1 : 0;
        }
        __syncthreads();
        if (s_last) {
            float r0 = __ldcg(yp + 0);
            float r1 = __ldcg(yp + 1);
            float r2 = __ldcg(yp + 2);
            float r3 = __ldcg(yp + 3);
            yp[0] = fmaxf(r0, 0.0f);
            yp[1] = fmaxf(r1, 0.0f);
            yp[2] = fmaxf(r2, 0.0f);
            yp[3] = fmaxf(r3, 0.0f);
        }
    }
}

extern "C" void kernel_launch(void* const* d_in, const int* in_sizes, int n_in,
                              void* d_out, int out_size)
{
    const float* adj0 = (const float*)d_in[0];
    const float* adj1 = (const float*)d_in[1];
    const float* adj2 = (const float*)d_in[2];
    const float* nv   = (const float*)d_in[3];
    const float* w0_1 = (const float*)d_in[4];
    const float* w0_2 = (const float*)d_in[5];
    const float* w1_1 = (const float*)d_in[6];
    const float* w1_2 = (const float*)d_in[7];
    const float* w2_1 = (const float*)d_in[8];
    const float* w2_2 = (const float*)d_in[9];
    float* out = (float*)d_out;

    float *gx, *gv1;
    cudaGetSymbolAddress((void**)&gx,  g_x);
    cudaGetSymbolAddress((void**)&gv1, g_v1);

    dist_kernel<<<512, 256>>>(adj0, adj1, adj2, nv, out);

    dim3 grid(JBLK, KBLK, 3);
    gemv_kernel<0, 0><<<grid, GEMV_TPB>>>(gx,  w0_1, w1_1, w2_1, gv1);
    gemv_kernel<1, 1><<<grid, GEMV_TPB>>>(gv1, w0_2, w1_2, w2_2, out);
}